// round 1
// baseline (speedup 1.0000x reference)
#include <cuda_runtime.h>
#include <math.h>

#define HDIM 1024
#define SEQ  2048
#define BATCH 4
#define MTOT (BATCH * SEQ)   // 8192

// Scratch (allocation-free rule: __device__ globals)
__device__ float g_q[(size_t)MTOT * HDIM];
__device__ float g_k[(size_t)MTOT * HDIM];
__device__ float g_v[(size_t)MTOT * HDIM];
__device__ float g_p[(size_t)BATCH * SEQ * SEQ];

#define BM 64
#define BN 64
#define BK 16
// 256 threads, 16x16 layout, each thread computes a 4x4 micro-tile.

// ---------------------------------------------------------------------------
// NT GEMM body: C[m,n] = sum_k A[m,k] * B[n,k] (+ bias[n])
// A: M x K row-major, B: N x K row-major. M,N,K all divisible by tile dims.
// ---------------------------------------------------------------------------
__device__ __forceinline__ void gemm_nt_body(
    const float* __restrict__ A, const float* __restrict__ Bmat,
    const float* __restrict__ bias, float* __restrict__ C,
    int N, int K)
{
    __shared__ float As[BK][BM + 4];   // row stride 68 floats = 272B (16B aligned)
    __shared__ float Bs[BK][BN + 4];

    const int tid = threadIdx.x;          // 0..255
    const int tx = tid & 15;              // 0..15 -> n
    const int ty = tid >> 4;              // 0..15 -> m
    const int m0 = blockIdx.y * BM;
    const int n0 = blockIdx.x * BN;

    // load mapping: 64 rows x 16 cols per tile, float4 per thread
    const int lr = tid >> 2;              // 0..63 row within tile
    const int lk = (tid & 3) * 4;         // 0,4,8,12 col group

    float acc[4][4] = {};

    for (int k0 = 0; k0 < K; k0 += BK) {
        float4 av = *reinterpret_cast<const float4*>(A    + (size_t)(m0 + lr) * K + k0 + lk);
        float4 bv = *reinterpret_cast<const float4*>(Bmat + (size_t)(n0 + lr) * K + k0 + lk);
        As[lk + 0][lr] = av.x; As[lk + 1][lr] = av.y;
        As[lk + 2][lr] = av.z; As[lk + 3][lr] = av.w;
        Bs[lk + 0][lr] = bv.x; Bs[lk + 1][lr] = bv.y;
        Bs[lk + 2][lr] = bv.z; Bs[lk + 3][lr] = bv.w;
        __syncthreads();

        #pragma unroll
        for (int kk = 0; kk < BK; kk++) {
            float4 a = *reinterpret_cast<const float4*>(&As[kk][ty * 4]);
            float4 b = *reinterpret_cast<const float4*>(&Bs[kk][tx * 4]);
            float ar[4] = {a.x, a.y, a.z, a.w};
            float br[4] = {b.x, b.y, b.z, b.w};
            #pragma unroll
            for (int i = 0; i < 4; i++)
                #pragma unroll
                for (int j = 0; j < 4; j++)
                    acc[i][j] += ar[i] * br[j];
        }
        __syncthreads();
    }

    const int nbase = n0 + tx * 4;
    float4 badd = {0.f, 0.f, 0.f, 0.f};
    if (bias) badd = *reinterpret_cast<const float4*>(bias + nbase);
    #pragma unroll
    for (int i = 0; i < 4; i++) {
        int m = m0 + ty * 4 + i;
        float4 o;
        o.x = acc[i][0] + badd.x;
        o.y = acc[i][1] + badd.y;
        o.z = acc[i][2] + badd.z;
        o.w = acc[i][3] + badd.w;
        *reinterpret_cast<float4*>(C + (size_t)m * N + nbase) = o;
    }
}

// ---------------------------------------------------------------------------
// NN GEMM body: C[m,n] = sum_k A[m,k] * B[k,n]
// A: M x K row-major, B: K x N row-major.
// ---------------------------------------------------------------------------
__device__ __forceinline__ void gemm_nn_body(
    const float* __restrict__ A, const float* __restrict__ Bmat,
    float* __restrict__ C, int N, int K)
{
    __shared__ float As[BK][BM + 4];
    __shared__ float Bs[BK][BN + 4];

    const int tid = threadIdx.x;
    const int tx = tid & 15;
    const int ty = tid >> 4;
    const int m0 = blockIdx.y * BM;
    const int n0 = blockIdx.x * BN;

    const int lr = tid >> 2;              // A tile: row 0..63
    const int lk = (tid & 3) * 4;         // A tile: col group
    const int br_ = tid >> 4;             // B tile: row 0..15
    const int bc = (tid & 15) * 4;        // B tile: col group

    float acc[4][4] = {};

    for (int k0 = 0; k0 < K; k0 += BK) {
        float4 av = *reinterpret_cast<const float4*>(A + (size_t)(m0 + lr) * K + k0 + lk);
        As[lk + 0][lr] = av.x; As[lk + 1][lr] = av.y;
        As[lk + 2][lr] = av.z; As[lk + 3][lr] = av.w;
        float4 bv = *reinterpret_cast<const float4*>(Bmat + (size_t)(k0 + br_) * N + n0 + bc);
        *reinterpret_cast<float4*>(&Bs[br_][bc]) = bv;
        __syncthreads();

        #pragma unroll
        for (int kk = 0; kk < BK; kk++) {
            float4 a = *reinterpret_cast<const float4*>(&As[kk][ty * 4]);
            float4 b = *reinterpret_cast<const float4*>(&Bs[kk][tx * 4]);
            float ar[4] = {a.x, a.y, a.z, a.w};
            float br2[4] = {b.x, b.y, b.z, b.w};
            #pragma unroll
            for (int i = 0; i < 4; i++)
                #pragma unroll
                for (int j = 0; j < 4; j++)
                    acc[i][j] += ar[i] * br2[j];
        }
        __syncthreads();
    }

    const int nbase = n0 + tx * 4;
    #pragma unroll
    for (int i = 0; i < 4; i++) {
        int m = m0 + ty * 4 + i;
        float4 o = {acc[i][0], acc[i][1], acc[i][2], acc[i][3]};
        *reinterpret_cast<float4*>(C + (size_t)m * N + nbase) = o;
    }
}

// ---------------------------------------------------------------------------
// Kernels
// ---------------------------------------------------------------------------
__global__ void __launch_bounds__(256) qkv_kernel(
    const float* __restrict__ x,
    const float* __restrict__ Wq, const float* __restrict__ bq,
    const float* __restrict__ Wk, const float* __restrict__ bk,
    const float* __restrict__ Wv, const float* __restrict__ bv)
{
    const float* W; const float* b; float* out;
    if (blockIdx.z == 0)      { W = Wq; b = bq; out = g_q; }
    else if (blockIdx.z == 1) { W = Wk; b = bk; out = g_k; }
    else                      { W = Wv; b = bv; out = g_v; }
    gemm_nt_body(x, W, b, out, HDIM, HDIM);
}

__global__ void __launch_bounds__(256) scores_kernel()
{
    size_t off = (size_t)blockIdx.z * SEQ * HDIM;
    gemm_nt_body(g_q + off, g_k + off, nullptr,
                 g_p + (size_t)blockIdx.z * SEQ * SEQ, SEQ, HDIM);
}

__global__ void __launch_bounds__(256) softmax_kernel()
{
    const int row = blockIdx.x;                 // 0..BATCH*SEQ-1
    float* p = g_p + (size_t)row * SEQ;
    const int tid = threadIdx.x;

    float v[8];
    float m = -1e30f;
    #pragma unroll
    for (int i = 0; i < 8; i++) {
        v[i] = p[tid + i * 256];
        m = fmaxf(m, v[i]);
    }

    __shared__ float red[8];
    #pragma unroll
    for (int o = 16; o; o >>= 1) m = fmaxf(m, __shfl_xor_sync(0xffffffffu, m, o));
    if ((tid & 31) == 0) red[tid >> 5] = m;
    __syncthreads();
    m = red[0];
    #pragma unroll
    for (int i = 1; i < 8; i++) m = fmaxf(m, red[i]);
    __syncthreads();   // everyone done reading red before reuse

    float s = 0.f;
    #pragma unroll
    for (int i = 0; i < 8; i++) {
        v[i] = __expf(v[i] - m);
        s += v[i];
    }
    #pragma unroll
    for (int o = 16; o; o >>= 1) s += __shfl_xor_sync(0xffffffffu, s, o);
    if ((tid & 31) == 0) red[tid >> 5] = s;
    __syncthreads();
    float tot = 0.f;
    #pragma unroll
    for (int i = 0; i < 8; i++) tot += red[i];
    float inv = 1.0f / tot;

    #pragma unroll
    for (int i = 0; i < 8; i++) p[tid + i * 256] = v[i] * inv;
}

__global__ void __launch_bounds__(256) colsum_kernel(float* __restrict__ out)
{
    const int b = blockIdx.y;
    const int k = blockIdx.x * 256 + threadIdx.x;
    const float* p = g_p + (size_t)b * SEQ * SEQ + k;
    float s = 0.f;
    #pragma unroll 8
    for (int q = 0; q < SEQ; q++) s += p[(size_t)q * SEQ];
    out[b * SEQ + k] = s;
}

__global__ void __launch_bounds__(256) context_kernel(float* __restrict__ ctx)
{
    const int b = blockIdx.z;
    gemm_nn_body(g_p + (size_t)b * SEQ * SEQ,
                 g_v + (size_t)b * SEQ * HDIM,
                 ctx + (size_t)b * SEQ * HDIM, HDIM, SEQ);
}

// ---------------------------------------------------------------------------
extern "C" void kernel_launch(void* const* d_in, const int* in_sizes, int n_in,
                              void* d_out, int out_size)
{
    const float* x  = (const float*)d_in[0];
    const float* Wq = (const float*)d_in[1];
    const float* bq = (const float*)d_in[2];
    const float* Wk = (const float*)d_in[3];
    const float* bk = (const float*)d_in[4];
    const float* Wv = (const float*)d_in[5];
    const float* bv = (const float*)d_in[6];

    float* ctx = (float*)d_out;
    float* sc  = ctx + (size_t)BATCH * SEQ * HDIM;

    qkv_kernel<<<dim3(HDIM / BN, MTOT / BM, 3), 256>>>(x, Wq, bq, Wk, bk, Wv, bv);
    scores_kernel<<<dim3(SEQ / BN, SEQ / BM, BATCH), 256>>>();
    softmax_kernel<<<BATCH * SEQ, 256>>>();
    colsum_kernel<<<dim3(SEQ / 256, BATCH), 256>>>(sc);
    context_kernel<<<dim3(HDIM / BN, SEQ / BM, BATCH), 256>>>(ctx);
}

// round 5
// speedup vs baseline: 1.9240x; 1.9240x over previous
#include <cuda_runtime.h>
#include <cuda_bf16.h>
#include <stdint.h>

#define HDIM 1024
#define SEQ  2048
#define BATCH 4
#define MTOT (BATCH * SEQ)

typedef __nv_bfloat16 bf16;

// ---------------------------------------------------------------------------
// Scratch (__device__ globals: allocation-free rule). ~280 MB total.
// ---------------------------------------------------------------------------
__device__ bf16 g_xh[(size_t)MTOT * HDIM];
__device__ bf16 g_xl[(size_t)MTOT * HDIM];
__device__ bf16 g_wqh[(size_t)HDIM * HDIM], g_wql[(size_t)HDIM * HDIM];
__device__ bf16 g_wkh[(size_t)HDIM * HDIM], g_wkl[(size_t)HDIM * HDIM];
__device__ bf16 g_wvh[(size_t)HDIM * HDIM], g_wvl[(size_t)HDIM * HDIM];
__device__ bf16 g_qh[(size_t)MTOT * HDIM], g_ql[(size_t)MTOT * HDIM];
__device__ bf16 g_kh[(size_t)MTOT * HDIM], g_kl[(size_t)MTOT * HDIM];
__device__ bf16 g_vth[(size_t)BATCH * HDIM * SEQ], g_vtl[(size_t)BATCH * HDIM * SEQ];
__device__ float g_p[(size_t)BATCH * SEQ * SEQ];
__device__ bf16 g_ph[(size_t)BATCH * SEQ * SEQ], g_pl[(size_t)BATCH * SEQ * SEQ];

// ---------------------------------------------------------------------------
// Helpers
// ---------------------------------------------------------------------------
__device__ __forceinline__ uint32_t smem_u32(const void* p) {
    uint32_t a;
    asm("{ .reg .u64 t; cvta.to.shared.u64 t, %1; cvt.u32.u64 %0, t; }" : "=r"(a) : "l"(p));
    return a;
}

__device__ __forceinline__ void ldsm4(uint32_t* r, uint32_t addr) {
    asm volatile("ldmatrix.sync.aligned.m8n8.x4.shared.b16 {%0,%1,%2,%3}, [%4];"
                 : "=r"(r[0]), "=r"(r[1]), "=r"(r[2]), "=r"(r[3]) : "r"(addr));
}

__device__ __forceinline__ void mma16816(float* d, const uint32_t* a, uint32_t b0, uint32_t b1) {
    asm volatile("mma.sync.aligned.m16n8k16.row.col.f32.bf16.bf16.f32 "
                 "{%0,%1,%2,%3}, {%4,%5,%6,%7}, {%8,%9}, {%0,%1,%2,%3};"
                 : "+f"(d[0]), "+f"(d[1]), "+f"(d[2]), "+f"(d[3])
                 : "r"(a[0]), "r"(a[1]), "r"(a[2]), "r"(a[3]), "r"(b0), "r"(b1));
}

__device__ __forceinline__ void cpasync16(uint32_t dst, const void* src) {
    asm volatile("cp.async.cg.shared.global [%0], [%1], 16;" :: "r"(dst), "l"(src));
}
#define CP_COMMIT() asm volatile("cp.async.commit_group;" ::: "memory")
#define CP_WAIT1()  asm volatile("cp.async.wait_group 1;" ::: "memory")

__device__ __forceinline__ void split1(float v, bf16& h, bf16& l) {
    h = __float2bfloat16_rn(v);
    l = __float2bfloat16_rn(v - __bfloat162float(h));
}

// ---------------------------------------------------------------------------
// GEMM: C[m0+i, n0+j] = sum_k A[m0+i,k]*B[n0+j,k] with A=Ah+Al, B=Bh+Bl (bf16)
// using 3 bf16 HMMA products. CTA tile 128x256? -> 128x128, BK=32, 3 stages.
// Smem chunk layout: 16B chunk (r,cc) at (r&7)*16 + (cc + 4*(r>>3))*128.
// ---------------------------------------------------------------------------
#define BM 128
#define BN 128
#define BK 32
#define TILE_BYTES  8192            // 128 x 32 bf16
#define STAGE_BYTES (4 * TILE_BYTES)
#define SMEM_BYTES  (3 * STAGE_BYTES)

__device__ __forceinline__ uint32_t chunk_off(int r, int cc) {
    return (uint32_t)((r & 7) * 16 + (cc + 4 * (r >> 3)) * 128);
}

template <int MODE>   // 0: bf16 split row store +bias | 1: bf16 split transposed +bias | 2: fp32 row store
__device__ __forceinline__ void gemm_core(
    const bf16* __restrict__ Ah, const bf16* __restrict__ Al,
    const bf16* __restrict__ Bh, const bf16* __restrict__ Bl,
    int K, int lda, int ldb, const float* __restrict__ bias,
    bf16* __restrict__ outh, bf16* __restrict__ outl, float* __restrict__ outf,
    int ldc, int m0, int n0, int cm0)
{
    extern __shared__ char smem[];
    const uint32_t sb = smem_u32(smem);
    const int tid = threadIdx.x, lane = tid & 31, wid = tid >> 5;
    const int wm = wid & 1, wn = wid >> 1;   // 2 x 4 warps, warp tile 64x32

    float acc[4][4][4];
#pragma unroll
    for (int i = 0; i < 4; i++)
#pragma unroll
        for (int j = 0; j < 4; j++)
#pragma unroll
            for (int e = 0; e < 4; e++) acc[i][j][e] = 0.f;

    const int NC = K >> 5;

    // stage loader (8 cp.async of 16B per thread)
    auto issue = [&](int s) {
        const uint32_t base = sb + (uint32_t)(s % 3) * STAGE_BYTES;
        const int k0 = s * BK;
#pragma unroll
        for (int i = 0; i < 2; i++) {
            int id = tid + i * 256;
            int r = id >> 2, cc = id & 3;
            size_t go = (size_t)(m0 + r) * lda + (k0 + cc * 8);
            uint32_t so = base + chunk_off(r, cc);
            cpasync16(so,              Ah + go);
            cpasync16(so + TILE_BYTES, Al + go);
        }
#pragma unroll
        for (int i = 0; i < 2; i++) {
            int id = tid + i * 256;
            int r = id >> 2, cc = id & 3;
            size_t go = (size_t)(n0 + r) * ldb + (k0 + cc * 8);
            uint32_t so = base + 2 * TILE_BYTES + chunk_off(r, cc);
            cpasync16(so,              Bh + go);
            cpasync16(so + TILE_BYTES, Bl + go);
        }
    };

    issue(0); CP_COMMIT();
    issue(1); CP_COMMIT();

#pragma unroll 1
    for (int c = 0; c < NC; c++) {
        CP_WAIT1();
        __syncthreads();
        if (c + 2 < NC) issue(c + 2);
        CP_COMMIT();

        const uint32_t base = sb + (uint32_t)(c % 3) * STAGE_BYTES;
        const uint32_t lsel = (lane & 7) * 16 + ((lane >> 4)) * 128 + ((lane >> 3) & 1) * 512;

#pragma unroll
        for (int ks = 0; ks < 2; ks++) {
            const uint32_t koff = (uint32_t)(ks * 2) * 128;
            uint32_t ah[4][4], al[4][4];
#pragma unroll
            for (int mi = 0; mi < 4; mi++) {
                uint32_t g = (uint32_t)(wm * 8 + mi * 2);
                uint32_t off = base + lsel + koff + g * 512;
                ldsm4(ah[mi], off);
                ldsm4(al[mi], off + TILE_BYTES);
            }
            uint32_t bh[2][4], bl[2][4];
#pragma unroll
            for (int bi = 0; bi < 2; bi++) {
                uint32_t g = (uint32_t)(wn * 4 + bi * 2);
                uint32_t off = base + 2 * TILE_BYTES + lsel + koff + g * 512;
                ldsm4(bh[bi], off);
                ldsm4(bl[bi], off + TILE_BYTES);
            }
#pragma unroll
            for (int mi = 0; mi < 4; mi++)
#pragma unroll
                for (int ni = 0; ni < 4; ni++) {
                    const int bi = ni >> 1, j = ni & 1;
                    mma16816(acc[mi][ni], ah[mi], bh[bi][j], bh[bi][j + 2]);
                    mma16816(acc[mi][ni], ah[mi], bl[bi][j], bl[bi][j + 2]);
                    mma16816(acc[mi][ni], al[mi], bh[bi][j], bh[bi][j + 2]);
                }
        }
    }

    // epilogue — C frag: rows (lane>>2)+{0,8}, cols 2*(lane&3)+{0,1}
    const int rl = lane >> 2, cl = (lane & 3) * 2;
#pragma unroll
    for (int mi = 0; mi < 4; mi++)
#pragma unroll
        for (int ni = 0; ni < 4; ni++) {
            const int col = n0 + wn * 32 + ni * 8 + cl;
#pragma unroll
            for (int rh = 0; rh < 2; rh++) {
                float v0 = acc[mi][ni][rh * 2 + 0];
                float v1 = acc[mi][ni][rh * 2 + 1];
                if (MODE == 0 || MODE == 1) {
                    v0 += __ldg(bias + col);
                    v1 += __ldg(bias + col + 1);
                }
                if (MODE == 2) {
                    const int row = m0 + wm * 64 + mi * 16 + rl + rh * 8;
                    float2 o = {v0, v1};
                    *(float2*)(outf + (size_t)row * ldc + col) = o;
                } else if (MODE == 0) {
                    const int row = m0 + wm * 64 + mi * 16 + rl + rh * 8;
                    bf16 h0, l0, h1, l1;
                    split1(v0, h0, l0);
                    split1(v1, h1, l1);
                    uint32_t hp = ((uint32_t)__bfloat16_as_ushort(h1) << 16) | __bfloat16_as_ushort(h0);
                    uint32_t lp = ((uint32_t)__bfloat16_as_ushort(l1) << 16) | __bfloat16_as_ushort(l0);
                    size_t o = (size_t)row * ldc + col;
                    *(uint32_t*)((char*)outh + o * 2) = hp;
                    *(uint32_t*)((char*)outl + o * 2) = lp;
                } else {   // MODE 1: transposed store out[(col)*ldc + mloc]
                    const int mloc = cm0 + wm * 64 + mi * 16 + rl + rh * 8;
                    bf16 h0, l0, h1, l1;
                    split1(v0, h0, l0);
                    split1(v1, h1, l1);
                    outh[(size_t)col * ldc + mloc] = h0;
                    outl[(size_t)col * ldc + mloc] = l0;
                    outh[(size_t)(col + 1) * ldc + mloc] = h1;
                    outl[(size_t)(col + 1) * ldc + mloc] = l1;
                }
            }
        }
}

// ---------------------------------------------------------------------------
// Kernels
// ---------------------------------------------------------------------------
__global__ void __launch_bounds__(256) split_kernel(const float* __restrict__ src,
                                                    bf16* __restrict__ h,
                                                    bf16* __restrict__ l, int n4)
{
    int i = blockIdx.x * 256 + threadIdx.x;
    if (i >= n4) return;
    float4 v = ((const float4*)src)[i];
    float f[4] = {v.x, v.y, v.z, v.w};
    uint32_t hp[2], lp[2];
#pragma unroll
    for (int j = 0; j < 2; j++) {
        bf16 h0, l0, h1, l1;
        split1(f[2 * j + 0], h0, l0);
        split1(f[2 * j + 1], h1, l1);
        hp[j] = ((uint32_t)__bfloat16_as_ushort(h1) << 16) | __bfloat16_as_ushort(h0);
        lp[j] = ((uint32_t)__bfloat16_as_ushort(l1) << 16) | __bfloat16_as_ushort(l0);
    }
    ((uint2*)h)[i] = make_uint2(hp[0], hp[1]);
    ((uint2*)l)[i] = make_uint2(lp[0], lp[1]);
}

__global__ void __launch_bounds__(256, 1) qkv_tc(
    const float* __restrict__ bq, const float* __restrict__ bk, const float* __restrict__ bv)
{
    const int m0 = blockIdx.y * BM;
    const int n0 = blockIdx.x * BN;
    if (blockIdx.z == 0) {
        gemm_core<0>(g_xh, g_xl, g_wqh, g_wql, HDIM, HDIM, HDIM, bq,
                     g_qh, g_ql, nullptr, HDIM, m0, n0, 0);
    } else if (blockIdx.z == 1) {
        gemm_core<0>(g_xh, g_xl, g_wkh, g_wkl, HDIM, HDIM, HDIM, bk,
                     g_kh, g_kl, nullptr, HDIM, m0, n0, 0);
    } else {
        const int b = m0 >> 11;
        gemm_core<1>(g_xh, g_xl, g_wvh, g_wvl, HDIM, HDIM, HDIM, bv,
                     g_vth + (size_t)b * HDIM * SEQ, g_vtl + (size_t)b * HDIM * SEQ,
                     nullptr, SEQ, m0, n0, m0 & (SEQ - 1));
    }
}

__global__ void __launch_bounds__(256, 1) scores_tc()
{
    const int b = blockIdx.z;
    const size_t bo = (size_t)b * SEQ * HDIM;
    gemm_core<2>(g_qh + bo, g_ql + bo, g_kh + bo, g_kl + bo, HDIM, HDIM, HDIM,
                 nullptr, nullptr, nullptr, g_p + (size_t)b * SEQ * SEQ, SEQ,
                 blockIdx.y * BM, blockIdx.x * BN, 0);
}

__global__ void __launch_bounds__(256, 1) context_tc(float* __restrict__ ctx)
{
    const int b = blockIdx.z;
    gemm_core<2>(g_ph + (size_t)b * SEQ * SEQ, g_pl + (size_t)b * SEQ * SEQ,
                 g_vth + (size_t)b * HDIM * SEQ, g_vtl + (size_t)b * HDIM * SEQ,
                 SEQ, SEQ, SEQ, nullptr, nullptr, nullptr,
                 ctx + (size_t)b * SEQ * HDIM, HDIM,
                 blockIdx.y * BM, blockIdx.x * BN, 0);
}

__global__ void __launch_bounds__(256) softmax_kernel()
{
    const int row = blockIdx.x;
    const float* p = g_p + (size_t)row * SEQ;
    bf16* ph = g_ph + (size_t)row * SEQ;
    bf16* pl = g_pl + (size_t)row * SEQ;
    const int tid = threadIdx.x;

    float v[8];
    float m = -1e30f;
#pragma unroll
    for (int i = 0; i < 8; i++) {
        v[i] = p[tid + i * 256];
        m = fmaxf(m, v[i]);
    }
    __shared__ float red[8];
#pragma unroll
    for (int o = 16; o; o >>= 1) m = fmaxf(m, __shfl_xor_sync(0xffffffffu, m, o));
    if ((tid & 31) == 0) red[tid >> 5] = m;
    __syncthreads();
    m = red[0];
#pragma unroll
    for (int i = 1; i < 8; i++) m = fmaxf(m, red[i]);
    __syncthreads();

    float s = 0.f;
#pragma unroll
    for (int i = 0; i < 8; i++) {
        v[i] = __expf(v[i] - m);
        s += v[i];
    }
#pragma unroll
    for (int o = 16; o; o >>= 1) s += __shfl_xor_sync(0xffffffffu, s, o);
    if ((tid & 31) == 0) red[tid >> 5] = s;
    __syncthreads();
    float tot = 0.f;
#pragma unroll
    for (int i = 0; i < 8; i++) tot += red[i];
    float inv = 1.0f / tot;

#pragma unroll
    for (int i = 0; i < 8; i++) {
        float pr = v[i] * inv;
        bf16 h, l;
        split1(pr, h, l);
        ph[tid + i * 256] = h;
        pl[tid + i * 256] = l;
    }
}

__global__ void __launch_bounds__(256) colsum_kernel(float* __restrict__ out)
{
    const int b = blockIdx.z;
    const int k = blockIdx.x * 256 + threadIdx.x;
    const int q0 = blockIdx.y * 256;
    const bf16* ph = g_ph + (size_t)b * SEQ * SEQ + (size_t)q0 * SEQ + k;
    const bf16* pl = g_pl + (size_t)b * SEQ * SEQ + (size_t)q0 * SEQ + k;
    float s = 0.f;
#pragma unroll 8
    for (int q = 0; q < 256; q++) {
        s += __bfloat162float(ph[(size_t)q * SEQ]) + __bfloat162float(pl[(size_t)q * SEQ]);
    }
    atomicAdd(out + b * SEQ + k, s);
}

// ---------------------------------------------------------------------------
extern "C" void kernel_launch(void* const* d_in, const int* in_sizes, int n_in,
                              void* d_out, int out_size)
{
    const float* x  = (const float*)d_in[0];
    const float* Wq = (const float*)d_in[1];
    const float* bq = (const float*)d_in[2];
    const float* Wk = (const float*)d_in[3];
    const float* bk = (const float*)d_in[4];
    const float* Wv = (const float*)d_in[5];
    const float* bv = (const float*)d_in[6];

    float* ctx = (float*)d_out;
    float* sc  = ctx + (size_t)BATCH * SEQ * HDIM;

    cudaFuncSetAttribute((const void*)qkv_tc,
                         cudaFuncAttributeMaxDynamicSharedMemorySize, SMEM_BYTES);
    cudaFuncSetAttribute((const void*)scores_tc,
                         cudaFuncAttributeMaxDynamicSharedMemorySize, SMEM_BYTES);
    cudaFuncSetAttribute((const void*)context_tc,
                         cudaFuncAttributeMaxDynamicSharedMemorySize, SMEM_BYTES);

    bf16 *xh, *xl, *wqh, *wql, *wkh, *wkl, *wvh, *wvl;
    cudaGetSymbolAddress((void**)&xh,  g_xh);
    cudaGetSymbolAddress((void**)&xl,  g_xl);
    cudaGetSymbolAddress((void**)&wqh, g_wqh);
    cudaGetSymbolAddress((void**)&wql, g_wql);
    cudaGetSymbolAddress((void**)&wkh, g_wkh);
    cudaGetSymbolAddress((void**)&wkl, g_wkl);
    cudaGetSymbolAddress((void**)&wvh, g_wvh);
    cudaGetSymbolAddress((void**)&wvl, g_wvl);

    const int nx4 = (MTOT * HDIM) / 4;       // 2097152
    const int nw4 = (HDIM * HDIM) / 4;       // 262144
    split_kernel<<<(nx4 + 255) / 256, 256>>>(x,  xh,  xl,  nx4);
    split_kernel<<<(nw4 + 255) / 256, 256>>>(Wq, wqh, wql, nw4);
    split_kernel<<<(nw4 + 255) / 256, 256>>>(Wk, wkh, wkl, nw4);
    split_kernel<<<(nw4 + 255) / 256, 256>>>(Wv, wvh, wvl, nw4);

    qkv_tc<<<dim3(HDIM / BN, MTOT / BM, 3), 256, SMEM_BYTES>>>(bq, bk, bv);
    scores_tc<<<dim3(SEQ / BN, SEQ / BM, BATCH), 256, SMEM_BYTES>>>();
    softmax_kernel<<<MTOT, 256>>>();
    cudaMemsetAsync(sc, 0, (size_t)BATCH * SEQ * sizeof(float));
    colsum_kernel<<<dim3(SEQ / 256, SEQ / 256, BATCH), 256>>>(sc);
    context_tc<<<dim3(HDIM / BN, SEQ / BM, BATCH), 256, SMEM_BYTES>>>(ctx);
}

// round 6
// speedup vs baseline: 1.9322x; 1.0043x over previous
#include <cuda_runtime.h>
#include <cuda_bf16.h>
#include <stdint.h>

#define HDIM 1024
#define SEQ  2048
#define BATCH 4
#define MTOT (BATCH * SEQ)

typedef __nv_bfloat16 bf16;

// ---------------------------------------------------------------------------
// Scratch (__device__ globals: allocation-free rule)
// ---------------------------------------------------------------------------
__device__ bf16 g_xh[(size_t)MTOT * HDIM];
__device__ bf16 g_xl[(size_t)MTOT * HDIM];
__device__ bf16 g_wqh[(size_t)HDIM * HDIM], g_wql[(size_t)HDIM * HDIM];
__device__ bf16 g_wkh[(size_t)HDIM * HDIM], g_wkl[(size_t)HDIM * HDIM];
__device__ bf16 g_wvh[(size_t)HDIM * HDIM], g_wvl[(size_t)HDIM * HDIM];
__device__ bf16 g_qh[(size_t)MTOT * HDIM], g_ql[(size_t)MTOT * HDIM];
__device__ bf16 g_kh[(size_t)MTOT * HDIM], g_kl[(size_t)MTOT * HDIM];
__device__ bf16 g_vth[(size_t)BATCH * HDIM * SEQ], g_vtl[(size_t)BATCH * HDIM * SEQ];
__device__ float g_p[(size_t)BATCH * SEQ * SEQ];
__device__ bf16 g_ph[(size_t)BATCH * SEQ * SEQ], g_pl[(size_t)BATCH * SEQ * SEQ];

// ---------------------------------------------------------------------------
// Helpers
// ---------------------------------------------------------------------------
__device__ __forceinline__ uint32_t smem_u32(const void* p) {
    uint32_t a;
    asm("{ .reg .u64 t; cvta.to.shared.u64 t, %1; cvt.u32.u64 %0, t; }" : "=r"(a) : "l"(p));
    return a;
}

__device__ __forceinline__ void ldsm4(uint32_t* r, uint32_t addr) {
    asm volatile("ldmatrix.sync.aligned.m8n8.x4.shared.b16 {%0,%1,%2,%3}, [%4];"
                 : "=r"(r[0]), "=r"(r[1]), "=r"(r[2]), "=r"(r[3]) : "r"(addr));
}

__device__ __forceinline__ void mma16816(float* d, const uint32_t* a, uint32_t b0, uint32_t b1) {
    asm volatile("mma.sync.aligned.m16n8k16.row.col.f32.bf16.bf16.f32 "
                 "{%0,%1,%2,%3}, {%4,%5,%6,%7}, {%8,%9}, {%0,%1,%2,%3};"
                 : "+f"(d[0]), "+f"(d[1]), "+f"(d[2]), "+f"(d[3])
                 : "r"(a[0]), "r"(a[1]), "r"(a[2]), "r"(a[3]), "r"(b0), "r"(b1));
}

__device__ __forceinline__ void cpasync16(uint32_t dst, const void* src) {
    asm volatile("cp.async.cg.shared.global [%0], [%1], 16;" :: "r"(dst), "l"(src));
}
#define CP_COMMIT() asm volatile("cp.async.commit_group;" ::: "memory")
#define CP_WAIT2()  asm volatile("cp.async.wait_group 2;" ::: "memory")

__device__ __forceinline__ void split1(float v, bf16& h, bf16& l) {
    h = __float2bfloat16_rn(v);
    l = __float2bfloat16_rn(v - __bfloat162float(h));
}

// ---------------------------------------------------------------------------
// GEMM: C[m0+i, n0+j] = sum_k A[m0+i,k]*B[n0+j,k], A=Ah+Al, B=Bh+Bl (bf16),
// 3 HMMA products, fp32 acc. CTA tile 128x256, 8 warps (2x4) of 64x64,
// BK=32, 4-stage cp.async ring.
// Chunk-contiguous smem: 16B chunk (r, cc) at (r&7)*16 + (cc + 4*(r>>3))*128.
// ---------------------------------------------------------------------------
#define BM 128
#define BN 256
#define BK 32
#define A_BYTES 8192               // 128 x 32 bf16
#define B_BYTES 16384              // 256 x 32 bf16
#define STAGE_BYTES (2 * A_BYTES + 2 * B_BYTES)   // Ah Al Bh Bl = 49152
#define NSTAGE 4
#define SMEM_BYTES (NSTAGE * STAGE_BYTES)         // 196608

__device__ __forceinline__ uint32_t chunk_off(int r, int cc) {
    return (uint32_t)((r & 7) * 16 + (cc + 4 * (r >> 3)) * 128);
}

template <int MODE>   // 0: bf16 split row +bias | 1: bf16 split transposed +bias | 2: fp32 row
__device__ __forceinline__ void gemm_core(
    const bf16* __restrict__ Ah, const bf16* __restrict__ Al,
    const bf16* __restrict__ Bh, const bf16* __restrict__ Bl,
    int K, int lda, int ldb, const float* __restrict__ bias,
    bf16* __restrict__ outh, bf16* __restrict__ outl, float* __restrict__ outf,
    int ldc, int m0, int n0, int cm0)
{
    extern __shared__ char smem[];
    const uint32_t sb = smem_u32(smem);
    const int tid = threadIdx.x, lane = tid & 31, wid = tid >> 5;
    const int wm = wid & 1, wn = wid >> 1;   // 2 x 4 warps, warp tile 64 x 64

    float acc[4][8][4];
#pragma unroll
    for (int i = 0; i < 4; i++)
#pragma unroll
        for (int j = 0; j < 8; j++)
#pragma unroll
            for (int e = 0; e < 4; e++) acc[i][j][e] = 0.f;

    const int NC = K >> 5;

    auto issue = [&](int s) {
        const uint32_t base = sb + (uint32_t)(s & (NSTAGE - 1)) * STAGE_BYTES;
        const int k0 = s * BK;
        // A: 512 chunks (h), 2 per thread
#pragma unroll
        for (int i = 0; i < 2; i++) {
            int id = tid + i * 256;
            int r = id >> 2, cc = id & 3;
            size_t go = (size_t)(m0 + r) * lda + (k0 + cc * 8);
            uint32_t so = base + chunk_off(r, cc);
            cpasync16(so,           Ah + go);
            cpasync16(so + A_BYTES, Al + go);
        }
        // B: 1024 chunks (h), 4 per thread
#pragma unroll
        for (int i = 0; i < 4; i++) {
            int id = tid + i * 256;
            int r = id >> 2, cc = id & 3;
            size_t go = (size_t)(n0 + r) * ldb + (k0 + cc * 8);
            uint32_t so = base + 2 * A_BYTES + chunk_off(r, cc);
            cpasync16(so,           Bh + go);
            cpasync16(so + B_BYTES, Bl + go);
        }
    };

    issue(0); CP_COMMIT();
    issue(1); CP_COMMIT();
    issue(2); CP_COMMIT();

    const uint32_t lsel = (lane & 7) * 16 + (lane >> 4) * 128 + ((lane >> 3) & 1) * 512;

#pragma unroll 1
    for (int c = 0; c < NC; c++) {
        CP_WAIT2();
        __syncthreads();
        if (c + 3 < NC) issue(c + 3);
        CP_COMMIT();

        const uint32_t base = sb + (uint32_t)(c & (NSTAGE - 1)) * STAGE_BYTES;

#pragma unroll
        for (int ks = 0; ks < 2; ks++) {
            const uint32_t koff = (uint32_t)ks * 256;
            uint32_t ah[4][4], al[4][4];
#pragma unroll
            for (int mi = 0; mi < 4; mi++) {
                uint32_t g = (uint32_t)(wm * 8 + mi * 2);
                uint32_t off = base + lsel + koff + g * 512;
                ldsm4(ah[mi], off);
                ldsm4(al[mi], off + A_BYTES);
            }
#pragma unroll
            for (int bi = 0; bi < 4; bi++) {
                uint32_t g = (uint32_t)(wn * 8 + bi * 2);
                uint32_t off = base + 2 * A_BYTES + lsel + koff + g * 512;
                uint32_t bh[4], bl[4];
                ldsm4(bh, off);
                ldsm4(bl, off + B_BYTES);
#pragma unroll
                for (int mi = 0; mi < 4; mi++)
#pragma unroll
                    for (int j = 0; j < 2; j++) {
                        const int ni = bi * 2 + j;
                        mma16816(acc[mi][ni], ah[mi], bh[j], bh[j + 2]);
                        mma16816(acc[mi][ni], ah[mi], bl[j], bl[j + 2]);
                        mma16816(acc[mi][ni], al[mi], bh[j], bh[j + 2]);
                    }
            }
        }
    }

    // epilogue — C frag: rows (lane>>2)+{0,8}, cols 2*(lane&3)+{0,1}
    const int rl = lane >> 2, cl = (lane & 3) * 2;
#pragma unroll
    for (int mi = 0; mi < 4; mi++)
#pragma unroll
        for (int ni = 0; ni < 8; ni++) {
            const int col = n0 + wn * 64 + ni * 8 + cl;
#pragma unroll
            for (int rh = 0; rh < 2; rh++) {
                float v0 = acc[mi][ni][rh * 2 + 0];
                float v1 = acc[mi][ni][rh * 2 + 1];
                if (MODE == 0 || MODE == 1) {
                    v0 += __ldg(bias + col);
                    v1 += __ldg(bias + col + 1);
                }
                if (MODE == 2) {
                    const int row = m0 + wm * 64 + mi * 16 + rl + rh * 8;
                    float2 o = {v0, v1};
                    *(float2*)(outf + (size_t)row * ldc + col) = o;
                } else if (MODE == 0) {
                    const int row = m0 + wm * 64 + mi * 16 + rl + rh * 8;
                    bf16 h0, l0, h1, l1;
                    split1(v0, h0, l0);
                    split1(v1, h1, l1);
                    uint32_t hp = ((uint32_t)__bfloat16_as_ushort(h1) << 16) | __bfloat16_as_ushort(h0);
                    uint32_t lp = ((uint32_t)__bfloat16_as_ushort(l1) << 16) | __bfloat16_as_ushort(l0);
                    size_t o = (size_t)row * ldc + col;
                    *(uint32_t*)((char*)outh + o * 2) = hp;
                    *(uint32_t*)((char*)outl + o * 2) = lp;
                } else {   // MODE 1: transposed store
                    const int mloc = cm0 + wm * 64 + mi * 16 + rl + rh * 8;
                    bf16 h0, l0, h1, l1;
                    split1(v0, h0, l0);
                    split1(v1, h1, l1);
                    outh[(size_t)col * ldc + mloc] = h0;
                    outl[(size_t)col * ldc + mloc] = l0;
                    outh[(size_t)(col + 1) * ldc + mloc] = h1;
                    outl[(size_t)(col + 1) * ldc + mloc] = l1;
                }
            }
        }
}

// ---------------------------------------------------------------------------
// Kernels
// ---------------------------------------------------------------------------
__global__ void __launch_bounds__(256) split_kernel(const float* __restrict__ src,
                                                    bf16* __restrict__ h,
                                                    bf16* __restrict__ l, int n4)
{
    int i = blockIdx.x * 256 + threadIdx.x;
    if (i >= n4) return;
    float4 v = ((const float4*)src)[i];
    float f[4] = {v.x, v.y, v.z, v.w};
    uint32_t hp[2], lp[2];
#pragma unroll
    for (int j = 0; j < 2; j++) {
        bf16 h0, l0, h1, l1;
        split1(f[2 * j + 0], h0, l0);
        split1(f[2 * j + 1], h1, l1);
        hp[j] = ((uint32_t)__bfloat16_as_ushort(h1) << 16) | __bfloat16_as_ushort(h0);
        lp[j] = ((uint32_t)__bfloat16_as_ushort(l1) << 16) | __bfloat16_as_ushort(l0);
    }
    ((uint2*)h)[i] = make_uint2(hp[0], hp[1]);
    ((uint2*)l)[i] = make_uint2(lp[0], lp[1]);
}

__global__ void __launch_bounds__(256, 1) qkv_tc(
    const float* __restrict__ bq, const float* __restrict__ bk, const float* __restrict__ bv)
{
    const int m0 = blockIdx.y * BM;
    const int n0 = blockIdx.x * BN;
    if (blockIdx.z == 0) {
        gemm_core<0>(g_xh, g_xl, g_wqh, g_wql, HDIM, HDIM, HDIM, bq,
                     g_qh, g_ql, nullptr, HDIM, m0, n0, 0);
    } else if (blockIdx.z == 1) {
        gemm_core<0>(g_xh, g_xl, g_wkh, g_wkl, HDIM, HDIM, HDIM, bk,
                     g_kh, g_kl, nullptr, HDIM, m0, n0, 0);
    } else {
        const int b = m0 >> 11;
        gemm_core<1>(g_xh, g_xl, g_wvh, g_wvl, HDIM, HDIM, HDIM, bv,
                     g_vth + (size_t)b * HDIM * SEQ, g_vtl + (size_t)b * HDIM * SEQ,
                     nullptr, SEQ, m0, n0, m0 & (SEQ - 1));
    }
}

__global__ void __launch_bounds__(256, 1) scores_tc()
{
    const int b = blockIdx.z;
    const size_t bo = (size_t)b * SEQ * HDIM;
    gemm_core<2>(g_qh + bo, g_ql + bo, g_kh + bo, g_kl + bo, HDIM, HDIM, HDIM,
                 nullptr, nullptr, nullptr, g_p + (size_t)b * SEQ * SEQ, SEQ,
                 blockIdx.y * BM, blockIdx.x * BN, 0);
}

__global__ void __launch_bounds__(256, 1) context_tc(float* __restrict__ ctx)
{
    const int b = blockIdx.z;
    gemm_core<2>(g_ph + (size_t)b * SEQ * SEQ, g_pl + (size_t)b * SEQ * SEQ,
                 g_vth + (size_t)b * HDIM * SEQ, g_vtl + (size_t)b * HDIM * SEQ,
                 SEQ, SEQ, SEQ, nullptr, nullptr, nullptr,
                 ctx + (size_t)b * SEQ * HDIM, HDIM,
                 blockIdx.y * BM, blockIdx.x * BN, 0);
}

__global__ void __launch_bounds__(256) softmax_kernel()
{
    const int row = blockIdx.x;
    const float* p = g_p + (size_t)row * SEQ;
    bf16* ph = g_ph + (size_t)row * SEQ;
    bf16* pl = g_pl + (size_t)row * SEQ;
    const int tid = threadIdx.x;

    float v[8];
    float m = -1e30f;
#pragma unroll
    for (int i = 0; i < 8; i++) {
        v[i] = p[tid + i * 256];
        m = fmaxf(m, v[i]);
    }
    __shared__ float red[8];
#pragma unroll
    for (int o = 16; o; o >>= 1) m = fmaxf(m, __shfl_xor_sync(0xffffffffu, m, o));
    if ((tid & 31) == 0) red[tid >> 5] = m;
    __syncthreads();
    m = red[0];
#pragma unroll
    for (int i = 1; i < 8; i++) m = fmaxf(m, red[i]);
    __syncthreads();

    float s = 0.f;
#pragma unroll
    for (int i = 0; i < 8; i++) {
        v[i] = __expf(v[i] - m);
        s += v[i];
    }
#pragma unroll
    for (int o = 16; o; o >>= 1) s += __shfl_xor_sync(0xffffffffu, s, o);
    if ((tid & 31) == 0) red[tid >> 5] = s;
    __syncthreads();
    float tot = 0.f;
#pragma unroll
    for (int i = 0; i < 8; i++) tot += red[i];
    float inv = 1.0f / tot;

#pragma unroll
    for (int i = 0; i < 8; i++) {
        float pr = v[i] * inv;
        bf16 h, l;
        split1(pr, h, l);
        ph[tid + i * 256] = h;
        pl[tid + i * 256] = l;
    }
}

__global__ void __launch_bounds__(256) colsum_kernel(float* __restrict__ out)
{
    const int b = blockIdx.z;
    const int k = blockIdx.x * 256 + threadIdx.x;
    const int q0 = blockIdx.y * 256;
    const bf16* ph = g_ph + (size_t)b * SEQ * SEQ + (size_t)q0 * SEQ + k;
    const bf16* pl = g_pl + (size_t)b * SEQ * SEQ + (size_t)q0 * SEQ + k;
    float s = 0.f;
#pragma unroll 8
    for (int q = 0; q < 256; q++) {
        s += __bfloat162float(ph[(size_t)q * SEQ]) + __bfloat162float(pl[(size_t)q * SEQ]);
    }
    atomicAdd(out + b * SEQ + k, s);
}

// ---------------------------------------------------------------------------
extern "C" void kernel_launch(void* const* d_in, const int* in_sizes, int n_in,
                              void* d_out, int out_size)
{
    const float* x  = (const float*)d_in[0];
    const float* Wq = (const float*)d_in[1];
    const float* bq = (const float*)d_in[2];
    const float* Wk = (const float*)d_in[3];
    const float* bk = (const float*)d_in[4];
    const float* Wv = (const float*)d_in[5];
    const float* bv = (const float*)d_in[6];

    float* ctx = (float*)d_out;
    float* sc  = ctx + (size_t)BATCH * SEQ * HDIM;

    cudaFuncSetAttribute((const void*)qkv_tc,
                         cudaFuncAttributeMaxDynamicSharedMemorySize, SMEM_BYTES);
    cudaFuncSetAttribute((const void*)scores_tc,
                         cudaFuncAttributeMaxDynamicSharedMemorySize, SMEM_BYTES);
    cudaFuncSetAttribute((const void*)context_tc,
                         cudaFuncAttributeMaxDynamicSharedMemorySize, SMEM_BYTES);

    bf16 *xh, *xl, *wqh, *wql, *wkh, *wkl, *wvh, *wvl;
    cudaGetSymbolAddress((void**)&xh,  g_xh);
    cudaGetSymbolAddress((void**)&xl,  g_xl);
    cudaGetSymbolAddress((void**)&wqh, g_wqh);
    cudaGetSymbolAddress((void**)&wql, g_wql);
    cudaGetSymbolAddress((void**)&wkh, g_wkh);
    cudaGetSymbolAddress((void**)&wkl, g_wkl);
    cudaGetSymbolAddress((void**)&wvh, g_wvh);
    cudaGetSymbolAddress((void**)&wvl, g_wvl);

    cudaMemsetAsync(sc, 0, (size_t)BATCH * SEQ * sizeof(float));

    const int nx4 = (MTOT * HDIM) / 4;
    const int nw4 = (HDIM * HDIM) / 4;
    split_kernel<<<(nx4 + 255) / 256, 256>>>(x,  xh,  xl,  nx4);
    split_kernel<<<(nw4 + 255) / 256, 256>>>(Wq, wqh, wql, nw4);
    split_kernel<<<(nw4 + 255) / 256, 256>>>(Wk, wkh, wkl, nw4);
    split_kernel<<<(nw4 + 255) / 256, 256>>>(Wv, wvh, wvl, nw4);

    qkv_tc<<<dim3(HDIM / BN, MTOT / BM, 3), 256, SMEM_BYTES>>>(bq, bk, bv);
    scores_tc<<<dim3(SEQ / BN, SEQ / BM, BATCH), 256, SMEM_BYTES>>>();
    softmax_kernel<<<MTOT, 256>>>();
    colsum_kernel<<<dim3(SEQ / 256, SEQ / 256, BATCH), 256>>>(sc);
    context_tc<<<dim3(HDIM / BN, SEQ / BM, BATCH), 256, SMEM_BYTES>>>(ctx);
}

// round 7
// speedup vs baseline: 3.0515x; 1.5793x over previous
#include <cuda_runtime.h>
#include <cuda_bf16.h>
#include <stdint.h>

#define HDIM 1024
#define SEQ  2048
#define BATCH 4
#define MTOT (BATCH * SEQ)

typedef __nv_bfloat16 bf16;

// ---------------------------------------------------------------------------
// Panel geometry
// A-role panels: 128 rows x 32 k, [h 8KB | l 8KB] = 16KB
// B-role panels: 256 rows x 32 k, [h 16KB | l 16KB] = 32KB
// Within each half: 16B chunk (r, cc) at (r&7)*16 + (cc + 4*(r>>3))*128
// ---------------------------------------------------------------------------
#define PANEL_A 16384
#define PANEL_B 32768

// Scratch (__device__ globals: allocation-free rule)
__device__ __align__(128) char g_xp [(size_t)64 * 32 * PANEL_A];            // x   A-role
__device__ __align__(128) char g_wqp[(size_t)4  * 32 * PANEL_B];            // Wq  B-role
__device__ __align__(128) char g_wkp[(size_t)4  * 32 * PANEL_B];
__device__ __align__(128) char g_wvp[(size_t)4  * 32 * PANEL_B];
__device__ __align__(128) char g_qp [(size_t)64 * 32 * PANEL_A];            // Q   A-role
__device__ __align__(128) char g_kp [(size_t)32 * 32 * PANEL_B];            // K   B-role
__device__ __align__(128) char g_vtp[(size_t)BATCH * 4 * 64 * PANEL_B];     // V^T B-role (per batch)
__device__ float g_p[(size_t)BATCH * SEQ * SEQ];                            // logits fp32
__device__ __align__(128) char g_pp [(size_t)64 * 64 * PANEL_A];            // probs A-role

// ---------------------------------------------------------------------------
// Helpers
// ---------------------------------------------------------------------------
__device__ __forceinline__ uint32_t smem_u32(const void* p) {
    uint32_t a;
    asm("{ .reg .u64 t; cvta.to.shared.u64 t, %1; cvt.u32.u64 %0, t; }" : "=r"(a) : "l"(p));
    return a;
}

__device__ __forceinline__ void ldsm4(uint32_t* r, uint32_t addr) {
    asm volatile("ldmatrix.sync.aligned.m8n8.x4.shared.b16 {%0,%1,%2,%3}, [%4];"
                 : "=r"(r[0]), "=r"(r[1]), "=r"(r[2]), "=r"(r[3]) : "r"(addr));
}

__device__ __forceinline__ void mma16816(float* d, const uint32_t* a, uint32_t b0, uint32_t b1) {
    asm volatile("mma.sync.aligned.m16n8k16.row.col.f32.bf16.bf16.f32 "
                 "{%0,%1,%2,%3}, {%4,%5,%6,%7}, {%8,%9}, {%0,%1,%2,%3};"
                 : "+f"(d[0]), "+f"(d[1]), "+f"(d[2]), "+f"(d[3])
                 : "r"(a[0]), "r"(a[1]), "r"(a[2]), "r"(a[3]), "r"(b0), "r"(b1));
}

__device__ __forceinline__ void bulk_g2s(uint32_t dst, const void* src, uint32_t bytes, uint32_t mbar) {
    asm volatile("cp.async.bulk.shared::cluster.global.mbarrier::complete_tx::bytes "
                 "[%0], [%1], %2, [%3];"
                 :: "r"(dst), "l"(src), "r"(bytes), "r"(mbar) : "memory");
}

#define MBAR_INIT(addr, cnt) \
    asm volatile("mbarrier.init.shared.b64 [%0], %1;" :: "r"(addr), "r"(cnt) : "memory")
#define MBAR_EXPECT_TX(addr, tx) \
    asm volatile("mbarrier.arrive.expect_tx.shared::cta.b64 _, [%0], %1;" :: "r"(addr), "r"(tx) : "memory")
#define FENCE_ASYNC_SHARED() asm volatile("fence.proxy.async.shared::cta;" ::: "memory")

#define MBAR_WAIT_PARITY(addr, par) do {                                             \
    uint32_t _mbar = (uint32_t)(addr);                                               \
    uint32_t _par  = (uint32_t)(par);                                                \
    uint32_t _done;                                                                  \
    asm volatile("{\n\t.reg .pred p;\n\t"                                            \
        "mbarrier.try_wait.parity.acquire.cta.shared::cta.b64 p, [%1], %2;\n\t"      \
        "selp.b32 %0, 1, 0, p;\n\t}"                                                 \
        : "=r"(_done) : "r"(_mbar), "r"(_par) : "memory");                           \
    if (!_done) {                                                                    \
        asm volatile("{\n\t.reg .pred P1;\n\t"                                       \
            "WAIT_LOOP_%=:\n\t"                                                      \
            "mbarrier.try_wait.parity.acquire.cta.shared::cta.b64 P1, [%0], %1, 0x989680;\n\t" \
            "@P1 bra.uni WAIT_DONE_%=;\n\t"                                          \
            "bra.uni WAIT_LOOP_%=;\n\t"                                              \
            "WAIT_DONE_%=:\n\t}"                                                     \
            :: "r"(_mbar), "r"(_par) : "memory");                                    \
    }                                                                                \
} while (0)

__device__ __forceinline__ void split1(float v, bf16& h, bf16& l) {
    h = __float2bfloat16_rn(v);
    l = __float2bfloat16_rn(v - __bfloat162float(h));
}

__device__ __host__ __forceinline__ uint32_t chunk_off(int r, int cc) {
    return (uint32_t)((r & 7) * 16 + (cc + 4 * (r >> 3)) * 128);
}

// ---------------------------------------------------------------------------
// GEMM: C[m0+i, n0+j] = sum_k A[m0+i,k]*B[n0+j,k], operands pre-packed panels.
// CTA 128x256, 8 warps (2x4) of 64x64, BK=32, 4-stage bulk-copy ring.
// Stage layout: [Ah 8K][Al 8K][Bh 16K][Bl 16K] = 48KB.
// ---------------------------------------------------------------------------
#define STAGE_BYTES 49152
#define NSTAGE 4
#define SMEM_BYTES (1024 + NSTAGE * STAGE_BYTES)   // 197632

// MODE 0: A-role split panels +bias | 1: B-role split panels +bias
// MODE 2: fp32 row store            | 3: B-role transposed split panels +bias
template <int MODE>
__device__ __forceinline__ void gemm_core(
    const char* __restrict__ Ap, const char* __restrict__ Bp,
    int K, const float* __restrict__ bias,
    char* __restrict__ outp, float* __restrict__ outf,
    int ldc, int m0, int n0, int cm0)
{
    extern __shared__ char smem[];
    const uint32_t sb = smem_u32(smem);
    const int tid = threadIdx.x, lane = tid & 31, wid = tid >> 5;
    const int wm = wid & 1, wn = wid >> 1;

    float acc[4][8][4];
#pragma unroll
    for (int i = 0; i < 4; i++)
#pragma unroll
        for (int j = 0; j < 8; j++)
#pragma unroll
            for (int e = 0; e < 4; e++) acc[i][j][e] = 0.f;

    const int NC = K >> 5;
    const size_t a_base = (size_t)(m0 >> 7) * NC;
    const size_t b_base = (size_t)(n0 >> 8) * NC;

    if (tid == 0) {
#pragma unroll
        for (int s = 0; s < NSTAGE; s++) MBAR_INIT(sb + s * 8, 1);
    }
    __syncthreads();
    FENCE_ASYNC_SHARED();

    auto issue = [&](int s) {
        const uint32_t mb  = sb + (uint32_t)(s & 3) * 8;
        const uint32_t dst = sb + 1024 + (uint32_t)(s & 3) * STAGE_BYTES;
        MBAR_EXPECT_TX(mb, (uint32_t)STAGE_BYTES);
        bulk_g2s(dst,         Ap + (a_base + s) * PANEL_A, PANEL_A, mb);
        bulk_g2s(dst + PANEL_A, Bp + (b_base + s) * PANEL_B, PANEL_B, mb);
    };

    if (tid == 0) { issue(0); issue(1); issue(2); }

    const uint32_t lsel = (lane & 7) * 16 + (lane >> 4) * 128 + ((lane >> 3) & 1) * 512;

#pragma unroll 1
    for (int c = 0; c < NC; c++) {
        MBAR_WAIT_PARITY(sb + (c & 3) * 8, (c >> 2) & 1);
        __syncthreads();
        if (tid == 0 && c + 3 < NC) issue(c + 3);

        const uint32_t base = sb + 1024 + (uint32_t)(c & 3) * STAGE_BYTES;

#pragma unroll
        for (int ks = 0; ks < 2; ks++) {
            const uint32_t koff = (uint32_t)ks * 256;
            uint32_t ah[4][4], al[4][4];
#pragma unroll
            for (int mi = 0; mi < 4; mi++) {
                uint32_t g = (uint32_t)(wm * 8 + mi * 2);
                uint32_t off = base + lsel + koff + g * 512;
                ldsm4(ah[mi], off);
                ldsm4(al[mi], off + 8192);
            }
#pragma unroll
            for (int bi = 0; bi < 4; bi++) {
                uint32_t g = (uint32_t)(wn * 8 + bi * 2);
                uint32_t off = base + 16384 + lsel + koff + g * 512;
                uint32_t bh[4], bl[4];
                ldsm4(bh, off);
                ldsm4(bl, off + 16384);
#pragma unroll
                for (int mi = 0; mi < 4; mi++)
#pragma unroll
                    for (int j = 0; j < 2; j++) {
                        const int ni = bi * 2 + j;
                        mma16816(acc[mi][ni], ah[mi], bh[j], bh[j + 2]);
                        mma16816(acc[mi][ni], ah[mi], bl[j], bl[j + 2]);
                        mma16816(acc[mi][ni], al[mi], bh[j], bh[j + 2]);
                    }
            }
        }
    }

    // epilogue — C frag: rows (lane>>2)+{0,8}, cols 2*(lane&3)+{0,1}
    const int rl = lane >> 2, cl = (lane & 3) * 2;
#pragma unroll
    for (int mi = 0; mi < 4; mi++)
#pragma unroll
        for (int ni = 0; ni < 8; ni++) {
            const int col = n0 + wn * 64 + ni * 8 + cl;
#pragma unroll
            for (int rh = 0; rh < 2; rh++) {
                float v0 = acc[mi][ni][rh * 2 + 0];
                float v1 = acc[mi][ni][rh * 2 + 1];
                if (MODE != 2) {
                    v0 += __ldg(bias + col);
                    v1 += __ldg(bias + col + 1);
                }
                const int row = m0 + wm * 64 + mi * 16 + rl + rh * 8;
                if (MODE == 2) {
                    float2 o = {v0, v1};
                    *(float2*)(outf + (size_t)row * ldc + col) = o;
                } else if (MODE == 0) {   // A-role panels, k-width = ldc
                    bf16 h0, l0, h1, l1;
                    split1(v0, h0, l0); split1(v1, h1, l1);
                    uint32_t hp = ((uint32_t)__bfloat16_as_ushort(h1) << 16) | __bfloat16_as_ushort(h0);
                    uint32_t lp = ((uint32_t)__bfloat16_as_ushort(l1) << 16) | __bfloat16_as_ushort(l0);
                    size_t off = ((size_t)(row >> 7) * (ldc >> 5) + (col >> 5)) * PANEL_A
                               + chunk_off(row & 127, (col & 31) >> 3) + (col & 7) * 2;
                    *(uint32_t*)(outp + off)        = hp;
                    *(uint32_t*)(outp + off + 8192) = lp;
                } else if (MODE == 1) {   // B-role panels, k-width = ldc
                    bf16 h0, l0, h1, l1;
                    split1(v0, h0, l0); split1(v1, h1, l1);
                    uint32_t hp = ((uint32_t)__bfloat16_as_ushort(h1) << 16) | __bfloat16_as_ushort(h0);
                    uint32_t lp = ((uint32_t)__bfloat16_as_ushort(l1) << 16) | __bfloat16_as_ushort(l0);
                    size_t off = ((size_t)(row >> 8) * (ldc >> 5) + (col >> 5)) * PANEL_B
                               + chunk_off(row & 255, (col & 31) >> 3) + (col & 7) * 2;
                    *(uint32_t*)(outp + off)         = hp;
                    *(uint32_t*)(outp + off + 16384) = lp;
                } else {                  // MODE 3: V^T, B-role rows = col(h), k = local seq
                    const int mloc = cm0 + wm * 64 + mi * 16 + rl + rh * 8;
                    bf16 h0, l0, h1, l1;
                    split1(v0, h0, l0); split1(v1, h1, l1);
                    size_t pb = ((size_t)(col >> 8) * (SEQ >> 5) + (mloc >> 5)) * PANEL_B;
                    uint32_t co0 = chunk_off(col & 255, (mloc & 31) >> 3) + (mloc & 7) * 2;
                    uint32_t co1 = chunk_off((col + 1) & 255, (mloc & 31) >> 3) + (mloc & 7) * 2;
                    *(bf16*)(outp + pb + co0)         = h0;
                    *(bf16*)(outp + pb + co0 + 16384) = l0;
                    *(bf16*)(outp + pb + co1)         = h1;
                    *(bf16*)(outp + pb + co1 + 16384) = l1;
                }
            }
        }
}

// ---------------------------------------------------------------------------
// Split kernels: fp32 -> packed hi/lo panels
// ---------------------------------------------------------------------------
__global__ void __launch_bounds__(256) split_a_kernel(const float* __restrict__ src,
                                                      char* __restrict__ dst)
{   // rows x 1024, A-role
    int i = blockIdx.x * 256 + threadIdx.x;
    int idx = i * 4;
    int row = idx >> 10, k = idx & 1023;
    float4 v = *(const float4*)(src + idx);
    float f[4] = {v.x, v.y, v.z, v.w};
    uint32_t hp[2], lp[2];
#pragma unroll
    for (int j = 0; j < 2; j++) {
        bf16 h0, l0, h1, l1;
        split1(f[2 * j], h0, l0); split1(f[2 * j + 1], h1, l1);
        hp[j] = ((uint32_t)__bfloat16_as_ushort(h1) << 16) | __bfloat16_as_ushort(h0);
        lp[j] = ((uint32_t)__bfloat16_as_ushort(l1) << 16) | __bfloat16_as_ushort(l0);
    }
    size_t off = ((size_t)(row >> 7) * 32 + (k >> 5)) * PANEL_A
               + chunk_off(row & 127, (k & 31) >> 3) + (k & 7) * 2;
    *(uint2*)(dst + off)        = make_uint2(hp[0], hp[1]);
    *(uint2*)(dst + off + 8192) = make_uint2(lp[0], lp[1]);
}

__global__ void __launch_bounds__(256) split_b_kernel(const float* __restrict__ src,
                                                      char* __restrict__ dst)
{   // rows x 1024, B-role
    int i = blockIdx.x * 256 + threadIdx.x;
    int idx = i * 4;
    int row = idx >> 10, k = idx & 1023;
    float4 v = *(const float4*)(src + idx);
    float f[4] = {v.x, v.y, v.z, v.w};
    uint32_t hp[2], lp[2];
#pragma unroll
    for (int j = 0; j < 2; j++) {
        bf16 h0, l0, h1, l1;
        split1(f[2 * j], h0, l0); split1(f[2 * j + 1], h1, l1);
        hp[j] = ((uint32_t)__bfloat16_as_ushort(h1) << 16) | __bfloat16_as_ushort(h0);
        lp[j] = ((uint32_t)__bfloat16_as_ushort(l1) << 16) | __bfloat16_as_ushort(l0);
    }
    size_t off = ((size_t)(row >> 8) * 32 + (k >> 5)) * PANEL_B
               + chunk_off(row & 255, (k & 31) >> 3) + (k & 7) * 2;
    *(uint2*)(dst + off)         = make_uint2(hp[0], hp[1]);
    *(uint2*)(dst + off + 16384) = make_uint2(lp[0], lp[1]);
}

// ---------------------------------------------------------------------------
// GEMM kernels
// ---------------------------------------------------------------------------
__global__ void __launch_bounds__(256, 1) qkv_tc(
    const float* __restrict__ bq, const float* __restrict__ bk, const float* __restrict__ bv)
{
    const int m0 = blockIdx.y * 128;
    const int n0 = blockIdx.x * 256;
    if (blockIdx.z == 0) {
        gemm_core<0>(g_xp, g_wqp, HDIM, bq, g_qp, nullptr, HDIM, m0, n0, 0);
    } else if (blockIdx.z == 1) {
        gemm_core<1>(g_xp, g_wkp, HDIM, bk, g_kp, nullptr, HDIM, m0, n0, 0);
    } else {
        const int b = m0 >> 11;
        gemm_core<3>(g_xp, g_wvp, HDIM, bv,
                     g_vtp + (size_t)b * 4 * 64 * PANEL_B, nullptr, SEQ,
                     m0, n0, m0 & (SEQ - 1));
    }
}

__global__ void __launch_bounds__(256, 1) scores_tc()
{
    const int b = blockIdx.z;
    gemm_core<2>(g_qp + (size_t)b * 16 * 32 * PANEL_A,
                 g_kp + (size_t)b * 8 * 32 * PANEL_B,
                 HDIM, nullptr, nullptr,
                 g_p + (size_t)b * SEQ * SEQ, SEQ,
                 blockIdx.y * 128, blockIdx.x * 256, 0);
}

__global__ void __launch_bounds__(256, 1) context_tc(float* __restrict__ ctx)
{
    const int b = blockIdx.z;
    gemm_core<2>(g_pp + (size_t)b * 16 * 64 * PANEL_A,
                 g_vtp + (size_t)b * 4 * 64 * PANEL_B,
                 SEQ, nullptr, nullptr,
                 ctx + (size_t)b * SEQ * HDIM, HDIM,
                 blockIdx.y * 128, blockIdx.x * 256, 0);
}

// ---------------------------------------------------------------------------
// Softmax: fp32 logits -> split probs in A-role panels
// ---------------------------------------------------------------------------
__global__ void __launch_bounds__(256) softmax_kernel()
{
    const int row = blockIdx.x;
    const float* p = g_p + (size_t)row * SEQ;
    const int tid = threadIdx.x;

    float v[8];
    float m = -1e30f;
#pragma unroll
    for (int i = 0; i < 8; i++) {
        v[i] = p[tid + i * 256];
        m = fmaxf(m, v[i]);
    }
    __shared__ float red[8];
#pragma unroll
    for (int o = 16; o; o >>= 1) m = fmaxf(m, __shfl_xor_sync(0xffffffffu, m, o));
    if ((tid & 31) == 0) red[tid >> 5] = m;
    __syncthreads();
    m = red[0];
#pragma unroll
    for (int i = 1; i < 8; i++) m = fmaxf(m, red[i]);
    __syncthreads();

    float s = 0.f;
#pragma unroll
    for (int i = 0; i < 8; i++) {
        v[i] = __expf(v[i] - m);
        s += v[i];
    }
#pragma unroll
    for (int o = 16; o; o >>= 1) s += __shfl_xor_sync(0xffffffffu, s, o);
    if ((tid & 31) == 0) red[tid >> 5] = s;
    __syncthreads();
    float tot = 0.f;
#pragma unroll
    for (int i = 0; i < 8; i++) tot += red[i];
    float inv = 1.0f / tot;

    const size_t prow = (size_t)(row >> 7) * 64;
    const uint32_t cr = chunk_off(row & 127, 0);
#pragma unroll
    for (int i = 0; i < 8; i++) {
        const int col = tid + i * 256;
        float pr = v[i] * inv;
        bf16 h, l;
        split1(pr, h, l);
        size_t off = (prow + (col >> 5)) * PANEL_A
                   + (cr + ((col & 31) >> 3) * 128) + (col & 7) * 2;
        *(bf16*)(g_pp + off)        = h;
        *(bf16*)(g_pp + off + 8192) = l;
    }
}

// ---------------------------------------------------------------------------
// Column sums of probs, per-panel reduction
// ---------------------------------------------------------------------------
__global__ void __launch_bounds__(256) colsum_kernel(float* __restrict__ out)
{
    const int pk = blockIdx.x;   // 0..63 k-panel
    const int pr = blockIdx.y;   // 0..63 row-panel
    const char* panel = g_pp + ((size_t)pr * 64 + pk) * PANEL_A;
    const int tid = threadIdx.x;
    const int col = tid & 31;
    const int rg  = tid >> 5;    // 8 groups of 16 rows

    const uint32_t cbase = ((col & 31) >> 3) * 128 + (col & 7) * 2;
    float s = 0.f;
#pragma unroll
    for (int r = rg * 16; r < rg * 16 + 16; r++) {
        uint32_t off = (uint32_t)((r & 7) * 16 + 4 * (r >> 3) * 128) + cbase;
        s += __bfloat162float(*(const bf16*)(panel + off))
           + __bfloat162float(*(const bf16*)(panel + off + 8192));
    }
    __shared__ float part[256];
    part[tid] = s;
    __syncthreads();
    if (tid < 32) {
        float t = 0.f;
#pragma unroll
        for (int j = 0; j < 8; j++) t += part[tid + 32 * j];
        const int batch = pr >> 4;
        atomicAdd(out + batch * SEQ + pk * 32 + tid, t);
    }
}

// ---------------------------------------------------------------------------
extern "C" void kernel_launch(void* const* d_in, const int* in_sizes, int n_in,
                              void* d_out, int out_size)
{
    const float* x  = (const float*)d_in[0];
    const float* Wq = (const float*)d_in[1];
    const float* bq = (const float*)d_in[2];
    const float* Wk = (const float*)d_in[3];
    const float* bk = (const float*)d_in[4];
    const float* Wv = (const float*)d_in[5];
    const float* bv = (const float*)d_in[6];

    float* ctx = (float*)d_out;
    float* sc  = ctx + (size_t)BATCH * SEQ * HDIM;

    cudaFuncSetAttribute((const void*)qkv_tc,
                         cudaFuncAttributeMaxDynamicSharedMemorySize, SMEM_BYTES);
    cudaFuncSetAttribute((const void*)scores_tc,
                         cudaFuncAttributeMaxDynamicSharedMemorySize, SMEM_BYTES);
    cudaFuncSetAttribute((const void*)context_tc,
                         cudaFuncAttributeMaxDynamicSharedMemorySize, SMEM_BYTES);

    char *xp, *wqp, *wkp, *wvp;
    cudaGetSymbolAddress((void**)&xp,  g_xp);
    cudaGetSymbolAddress((void**)&wqp, g_wqp);
    cudaGetSymbolAddress((void**)&wkp, g_wkp);
    cudaGetSymbolAddress((void**)&wvp, g_wvp);

    cudaMemsetAsync(sc, 0, (size_t)BATCH * SEQ * sizeof(float));

    split_a_kernel<<<(MTOT * HDIM / 4) / 256, 256>>>(x,  xp);
    split_b_kernel<<<(HDIM * HDIM / 4) / 256, 256>>>(Wq, wqp);
    split_b_kernel<<<(HDIM * HDIM / 4) / 256, 256>>>(Wk, wkp);
    split_b_kernel<<<(HDIM * HDIM / 4) / 256, 256>>>(Wv, wvp);

    qkv_tc<<<dim3(HDIM / 256, MTOT / 128, 3), 256, SMEM_BYTES>>>(bq, bk, bv);
    scores_tc<<<dim3(SEQ / 256, SEQ / 128, BATCH), 256, SMEM_BYTES>>>();
    softmax_kernel<<<MTOT, 256>>>();
    colsum_kernel<<<dim3(64, 64), 256>>>(sc);
    context_tc<<<dim3(HDIM / 256, SEQ / 128, BATCH), 256, SMEM_BYTES>>>(ctx);
}

// round 8
// speedup vs baseline: 3.1625x; 1.0364x over previous
#include <cuda_runtime.h>
#include <cuda_bf16.h>
#include <stdint.h>

#define HDIM 1024
#define SEQ  2048
#define BATCH 4
#define MTOT (BATCH * SEQ)

typedef __nv_bfloat16 bf16;

// ---------------------------------------------------------------------------
// Panel geometry
// A-role panels: 128 rows x 32 k, [h 8KB | l 8KB] = 16KB
// B-role panels: 256 rows x 32 k, [h 16KB | l 16KB] = 32KB
// Within each half: 16B chunk (r, cc) at (r&7)*16 + (cc + 4*(r>>3))*128
// ---------------------------------------------------------------------------
#define PANEL_A 16384
#define PANEL_B 32768

// Scratch (__device__ globals: allocation-free rule)
__device__ __align__(128) char g_xp [(size_t)64 * 32 * PANEL_A];            // x   A-role
__device__ __align__(128) char g_wqp[(size_t)4  * 32 * PANEL_B];            // Wq  B-role
__device__ __align__(128) char g_wkp[(size_t)4  * 32 * PANEL_B];
__device__ __align__(128) char g_wvp[(size_t)4  * 32 * PANEL_B];
__device__ __align__(128) char g_qp [(size_t)64 * 32 * PANEL_A];            // Q   A-role
__device__ __align__(128) char g_kp [(size_t)32 * 32 * PANEL_B];            // K   B-role
__device__ __align__(128) char g_vtp[(size_t)BATCH * 4 * 64 * PANEL_B];     // V^T B-role
__device__ float g_p[(size_t)BATCH * SEQ * SEQ];                            // logits fp32
__device__ __align__(128) char g_pp [(size_t)64 * 64 * PANEL_A];            // probs A-role

// ---------------------------------------------------------------------------
// Helpers
// ---------------------------------------------------------------------------
__device__ __forceinline__ uint32_t smem_u32(const void* p) {
    uint32_t a;
    asm("{ .reg .u64 t; cvta.to.shared.u64 t, %1; cvt.u32.u64 %0, t; }" : "=r"(a) : "l"(p));
    return a;
}

__device__ __forceinline__ void ldsm4(uint32_t* r, uint32_t addr) {
    asm volatile("ldmatrix.sync.aligned.m8n8.x4.shared.b16 {%0,%1,%2,%3}, [%4];"
                 : "=r"(r[0]), "=r"(r[1]), "=r"(r[2]), "=r"(r[3]) : "r"(addr));
}

__device__ __forceinline__ void mma16816(float* d, const uint32_t* a, uint32_t b0, uint32_t b1) {
    asm volatile("mma.sync.aligned.m16n8k16.row.col.f32.bf16.bf16.f32 "
                 "{%0,%1,%2,%3}, {%4,%5,%6,%7}, {%8,%9}, {%0,%1,%2,%3};"
                 : "+f"(d[0]), "+f"(d[1]), "+f"(d[2]), "+f"(d[3])
                 : "r"(a[0]), "r"(a[1]), "r"(a[2]), "r"(a[3]), "r"(b0), "r"(b1));
}

__device__ __forceinline__ void bulk_g2s(uint32_t dst, const void* src, uint32_t bytes, uint32_t mbar) {
    asm volatile("cp.async.bulk.shared::cluster.global.mbarrier::complete_tx::bytes "
                 "[%0], [%1], %2, [%3];"
                 :: "r"(dst), "l"(src), "r"(bytes), "r"(mbar) : "memory");
}

#define MBAR_INIT(addr, cnt) \
    asm volatile("mbarrier.init.shared.b64 [%0], %1;" :: "r"(addr), "r"(cnt) : "memory")
#define MBAR_EXPECT_TX(addr, tx) \
    asm volatile("mbarrier.arrive.expect_tx.shared::cta.b64 _, [%0], %1;" :: "r"(addr), "r"(tx) : "memory")
#define FENCE_ASYNC_SHARED() asm volatile("fence.proxy.async.shared::cta;" ::: "memory")

#define MBAR_WAIT_PARITY(addr, par) do {                                             \
    uint32_t _mbar = (uint32_t)(addr);                                               \
    uint32_t _par  = (uint32_t)(par);                                                \
    uint32_t _done;                                                                  \
    asm volatile("{\n\t.reg .pred p;\n\t"                                            \
        "mbarrier.try_wait.parity.acquire.cta.shared::cta.b64 p, [%1], %2;\n\t"      \
        "selp.b32 %0, 1, 0, p;\n\t}"                                                 \
        : "=r"(_done) : "r"(_mbar), "r"(_par) : "memory");                           \
    if (!_done) {                                                                    \
        asm volatile("{\n\t.reg .pred P1;\n\t"                                       \
            "WAIT_LOOP_%=:\n\t"                                                      \
            "mbarrier.try_wait.parity.acquire.cta.shared::cta.b64 P1, [%0], %1, 0x989680;\n\t" \
            "@P1 bra.uni WAIT_DONE_%=;\n\t"                                          \
            "bra.uni WAIT_LOOP_%=;\n\t"                                              \
            "WAIT_DONE_%=:\n\t}"                                                     \
            :: "r"(_mbar), "r"(_par) : "memory");                                    \
    }                                                                                \
} while (0)

__device__ __forceinline__ void split1(float v, bf16& h, bf16& l) {
    h = __float2bfloat16_rn(v);
    l = __float2bfloat16_rn(v - __bfloat162float(h));
}

__device__ __host__ __forceinline__ uint32_t chunk_off(int r, int cc) {
    return (uint32_t)((r & 7) * 16 + (cc + 4 * (r >> 3)) * 128);
}

// ---------------------------------------------------------------------------
// GEMM: C[m0+i, n0+j] = sum_k A[m0+i,k]*B[n0+j,k], pre-packed panel operands.
// CTA 128x256, 16 warps (4m x 4n) of 32x64, BK=32, 4-stage bulk-copy ring.
// Stage layout: [Ah 8K][Al 8K][Bh 16K][Bl 16K] = 48KB.
// ---------------------------------------------------------------------------
#define STAGE_BYTES 49152
#define NSTAGE 4
#define SMEM_BYTES (1024 + NSTAGE * STAGE_BYTES)   // 197632
#define NTHREADS 512

// MODE 0: A-role split panels +bias | 1: B-role split panels +bias
// MODE 2: fp32 row store            | 3: B-role transposed split panels +bias
template <int MODE>
__device__ __forceinline__ void gemm_core(
    const char* __restrict__ Ap, const char* __restrict__ Bp,
    int K, const float* __restrict__ bias,
    char* __restrict__ outp, float* __restrict__ outf,
    int ldc, int m0, int n0, int cm0)
{
    extern __shared__ char smem[];
    const uint32_t sb = smem_u32(smem);
    const int tid = threadIdx.x, lane = tid & 31, wid = tid >> 5;
    const int wm = wid & 3, wn = wid >> 2;   // 4 x 4 warps, warp tile 32 x 64

    float acc[2][8][4];
#pragma unroll
    for (int i = 0; i < 2; i++)
#pragma unroll
        for (int j = 0; j < 8; j++)
#pragma unroll
            for (int e = 0; e < 4; e++) acc[i][j][e] = 0.f;

    const int NC = K >> 5;
    const size_t a_base = (size_t)(m0 >> 7) * NC;
    const size_t b_base = (size_t)(n0 >> 8) * NC;

    if (tid == 0) {
#pragma unroll
        for (int s = 0; s < NSTAGE; s++) MBAR_INIT(sb + s * 8, 1);
    }
    __syncthreads();
    FENCE_ASYNC_SHARED();

    auto issue = [&](int s) {
        const uint32_t mb  = sb + (uint32_t)(s & 3) * 8;
        const uint32_t dst = sb + 1024 + (uint32_t)(s & 3) * STAGE_BYTES;
        MBAR_EXPECT_TX(mb, (uint32_t)STAGE_BYTES);
        bulk_g2s(dst,           Ap + (a_base + s) * PANEL_A, PANEL_A, mb);
        bulk_g2s(dst + PANEL_A, Bp + (b_base + s) * PANEL_B, PANEL_B, mb);
    };

    if (tid == 0) { issue(0); issue(1); issue(2); }

    const uint32_t lsel = (lane & 7) * 16 + (lane >> 4) * 128 + ((lane >> 3) & 1) * 512;

#pragma unroll 1
    for (int c = 0; c < NC; c++) {
        MBAR_WAIT_PARITY(sb + (c & 3) * 8, (c >> 2) & 1);
        __syncthreads();
        if (tid == 0 && c + 3 < NC) issue(c + 3);

        const uint32_t base = sb + 1024 + (uint32_t)(c & 3) * STAGE_BYTES;

#pragma unroll
        for (int ks = 0; ks < 2; ks++) {
            const uint32_t koff = (uint32_t)ks * 256;
            uint32_t ah[2][4], al[2][4];
#pragma unroll
            for (int mi = 0; mi < 2; mi++) {
                uint32_t g = (uint32_t)(wm * 4 + mi * 2);
                uint32_t off = base + lsel + koff + g * 512;
                ldsm4(ah[mi], off);
                ldsm4(al[mi], off + 8192);
            }
#pragma unroll
            for (int bi = 0; bi < 4; bi++) {
                uint32_t g = (uint32_t)(wn * 8 + bi * 2);
                uint32_t off = base + 16384 + lsel + koff + g * 512;
                uint32_t bh[4], bl[4];
                ldsm4(bh, off);
                ldsm4(bl, off + 16384);
#pragma unroll
                for (int mi = 0; mi < 2; mi++)
#pragma unroll
                    for (int j = 0; j < 2; j++) {
                        const int ni = bi * 2 + j;
                        mma16816(acc[mi][ni], ah[mi], bh[j], bh[j + 2]);
                        mma16816(acc[mi][ni], ah[mi], bl[j], bl[j + 2]);
                        mma16816(acc[mi][ni], al[mi], bh[j], bh[j + 2]);
                    }
            }
        }
    }

    // epilogue — C frag: rows (lane>>2)+{0,8}, cols 2*(lane&3)+{0,1}
    const int rl = lane >> 2, cl = (lane & 3) * 2;
#pragma unroll
    for (int mi = 0; mi < 2; mi++)
#pragma unroll
        for (int ni = 0; ni < 8; ni++) {
            const int col = n0 + wn * 64 + ni * 8 + cl;
#pragma unroll
            for (int rh = 0; rh < 2; rh++) {
                float v0 = acc[mi][ni][rh * 2 + 0];
                float v1 = acc[mi][ni][rh * 2 + 1];
                if (MODE != 2) {
                    v0 += __ldg(bias + col);
                    v1 += __ldg(bias + col + 1);
                }
                const int row = m0 + wm * 32 + mi * 16 + rl + rh * 8;
                if (MODE == 2) {
                    float2 o = {v0, v1};
                    *(float2*)(outf + (size_t)row * ldc + col) = o;
                } else if (MODE == 0) {   // A-role panels, k-width = ldc
                    bf16 h0, l0, h1, l1;
                    split1(v0, h0, l0); split1(v1, h1, l1);
                    uint32_t hp = ((uint32_t)__bfloat16_as_ushort(h1) << 16) | __bfloat16_as_ushort(h0);
                    uint32_t lp = ((uint32_t)__bfloat16_as_ushort(l1) << 16) | __bfloat16_as_ushort(l0);
                    size_t off = ((size_t)(row >> 7) * (ldc >> 5) + (col >> 5)) * PANEL_A
                               + chunk_off(row & 127, (col & 31) >> 3) + (col & 7) * 2;
                    *(uint32_t*)(outp + off)        = hp;
                    *(uint32_t*)(outp + off + 8192) = lp;
                } else if (MODE == 1) {   // B-role panels, k-width = ldc
                    bf16 h0, l0, h1, l1;
                    split1(v0, h0, l0); split1(v1, h1, l1);
                    uint32_t hp = ((uint32_t)__bfloat16_as_ushort(h1) << 16) | __bfloat16_as_ushort(h0);
                    uint32_t lp = ((uint32_t)__bfloat16_as_ushort(l1) << 16) | __bfloat16_as_ushort(l0);
                    size_t off = ((size_t)(row >> 8) * (ldc >> 5) + (col >> 5)) * PANEL_B
                               + chunk_off(row & 255, (col & 31) >> 3) + (col & 7) * 2;
                    *(uint32_t*)(outp + off)         = hp;
                    *(uint32_t*)(outp + off + 16384) = lp;
                } else {                  // MODE 3: V^T, B-role rows = col(h), k = local seq
                    const int mloc = cm0 + wm * 32 + mi * 16 + rl + rh * 8;
                    bf16 h0, l0, h1, l1;
                    split1(v0, h0, l0); split1(v1, h1, l1);
                    size_t pb = ((size_t)(col >> 8) * (SEQ >> 5) + (mloc >> 5)) * PANEL_B;
                    uint32_t co0 = chunk_off(col & 255, (mloc & 31) >> 3) + (mloc & 7) * 2;
                    uint32_t co1 = chunk_off((col + 1) & 255, (mloc & 31) >> 3) + (mloc & 7) * 2;
                    *(bf16*)(outp + pb + co0)         = h0;
                    *(bf16*)(outp + pb + co0 + 16384) = l0;
                    *(bf16*)(outp + pb + co1)         = h1;
                    *(bf16*)(outp + pb + co1 + 16384) = l1;
                }
            }
        }
}

// ---------------------------------------------------------------------------
// Fused split: one launch packs x (A-role) + Wq/Wk/Wv (B-role)
// ---------------------------------------------------------------------------
__global__ void __launch_bounds__(256) split_fused(
    const float* __restrict__ x, const float* __restrict__ Wq,
    const float* __restrict__ Wk, const float* __restrict__ Wv,
    char* __restrict__ xp, char* __restrict__ wqp,
    char* __restrict__ wkp, char* __restrict__ wvp)
{
    const int bid = blockIdx.x;
    const float* src;
    char* dst;
    int i;
    bool arole;
    if (bid < 8192) {            // x: 8192x1024 fp32, A-role
        src = x; dst = xp; i = bid * 256 + threadIdx.x; arole = true;
    } else {
        const int w = (bid - 8192) >> 10;
        const int b2 = (bid - 8192) & 1023;
        src = (w == 0) ? Wq : (w == 1) ? Wk : Wv;
        dst = (w == 0) ? wqp : (w == 1) ? wkp : wvp;
        i = b2 * 256 + threadIdx.x; arole = false;
    }
    const int idx = i * 4;
    const int row = idx >> 10, k = idx & 1023;
    float4 v = *(const float4*)(src + idx);
    float f[4] = {v.x, v.y, v.z, v.w};
    uint32_t hp[2], lp[2];
#pragma unroll
    for (int j = 0; j < 2; j++) {
        bf16 h0, l0, h1, l1;
        split1(f[2 * j], h0, l0); split1(f[2 * j + 1], h1, l1);
        hp[j] = ((uint32_t)__bfloat16_as_ushort(h1) << 16) | __bfloat16_as_ushort(h0);
        lp[j] = ((uint32_t)__bfloat16_as_ushort(l1) << 16) | __bfloat16_as_ushort(l0);
    }
    if (arole) {
        size_t off = ((size_t)(row >> 7) * 32 + (k >> 5)) * PANEL_A
                   + chunk_off(row & 127, (k & 31) >> 3) + (k & 7) * 2;
        *(uint2*)(dst + off)        = make_uint2(hp[0], hp[1]);
        *(uint2*)(dst + off + 8192) = make_uint2(lp[0], lp[1]);
    } else {
        size_t off = ((size_t)(row >> 8) * 32 + (k >> 5)) * PANEL_B
                   + chunk_off(row & 255, (k & 31) >> 3) + (k & 7) * 2;
        *(uint2*)(dst + off)         = make_uint2(hp[0], hp[1]);
        *(uint2*)(dst + off + 16384) = make_uint2(lp[0], lp[1]);
    }
}

// ---------------------------------------------------------------------------
// GEMM kernels
// ---------------------------------------------------------------------------
__global__ void __launch_bounds__(NTHREADS, 1) qkv_tc(
    const float* __restrict__ bq, const float* __restrict__ bk, const float* __restrict__ bv)
{
    const int m0 = blockIdx.y * 128;
    const int n0 = blockIdx.x * 256;
    if (blockIdx.z == 0) {
        gemm_core<0>(g_xp, g_wqp, HDIM, bq, g_qp, nullptr, HDIM, m0, n0, 0);
    } else if (blockIdx.z == 1) {
        gemm_core<1>(g_xp, g_wkp, HDIM, bk, g_kp, nullptr, HDIM, m0, n0, 0);
    } else {
        const int b = m0 >> 11;
        gemm_core<3>(g_xp, g_wvp, HDIM, bv,
                     g_vtp + (size_t)b * 4 * 64 * PANEL_B, nullptr, SEQ,
                     m0, n0, m0 & (SEQ - 1));
    }
}

__global__ void __launch_bounds__(NTHREADS, 1) scores_tc()
{
    const int b = blockIdx.z;
    gemm_core<2>(g_qp + (size_t)b * 16 * 32 * PANEL_A,
                 g_kp + (size_t)b * 8 * 32 * PANEL_B,
                 HDIM, nullptr, nullptr,
                 g_p + (size_t)b * SEQ * SEQ, SEQ,
                 blockIdx.y * 128, blockIdx.x * 256, 0);
}

__global__ void __launch_bounds__(NTHREADS, 1) context_tc(float* __restrict__ ctx)
{
    const int b = blockIdx.z;
    gemm_core<2>(g_pp + (size_t)b * 16 * 64 * PANEL_A,
                 g_vtp + (size_t)b * 4 * 64 * PANEL_B,
                 SEQ, nullptr, nullptr,
                 ctx + (size_t)b * SEQ * HDIM, HDIM,
                 blockIdx.y * 128, blockIdx.x * 256, 0);
}

// ---------------------------------------------------------------------------
// Softmax: fp32 logits -> split probs in A-role panels
// ---------------------------------------------------------------------------
__global__ void __launch_bounds__(256) softmax_kernel()
{
    const int row = blockIdx.x;
    const float* p = g_p + (size_t)row * SEQ;
    const int tid = threadIdx.x;

    float v[8];
    float m = -1e30f;
#pragma unroll
    for (int i = 0; i < 8; i++) {
        v[i] = p[tid + i * 256];
        m = fmaxf(m, v[i]);
    }
    __shared__ float red[8];
#pragma unroll
    for (int o = 16; o; o >>= 1) m = fmaxf(m, __shfl_xor_sync(0xffffffffu, m, o));
    if ((tid & 31) == 0) red[tid >> 5] = m;
    __syncthreads();
    m = red[0];
#pragma unroll
    for (int i = 1; i < 8; i++) m = fmaxf(m, red[i]);
    __syncthreads();

    float s = 0.f;
#pragma unroll
    for (int i = 0; i < 8; i++) {
        v[i] = __expf(v[i] - m);
        s += v[i];
    }
#pragma unroll
    for (int o = 16; o; o >>= 1) s += __shfl_xor_sync(0xffffffffu, s, o);
    if ((tid & 31) == 0) red[tid >> 5] = s;
    __syncthreads();
    float tot = 0.f;
#pragma unroll
    for (int i = 0; i < 8; i++) tot += red[i];
    float inv = 1.0f / tot;

    const size_t prow = (size_t)(row >> 7) * 64;
    const uint32_t cr = chunk_off(row & 127, 0);
#pragma unroll
    for (int i = 0; i < 8; i++) {
        const int col = tid + i * 256;
        float pr = v[i] * inv;
        bf16 h, l;
        split1(pr, h, l);
        size_t off = (prow + (col >> 5)) * PANEL_A
                   + (cr + ((col & 31) >> 3) * 128) + (col & 7) * 2;
        *(bf16*)(g_pp + off)        = h;
        *(bf16*)(g_pp + off + 8192) = l;
    }
}

// ---------------------------------------------------------------------------
// Column sums of probs, per-panel reduction
// ---------------------------------------------------------------------------
__global__ void __launch_bounds__(256) colsum_kernel(float* __restrict__ out)
{
    const int pk = blockIdx.x;   // 0..63 k-panel
    const int pr = blockIdx.y;   // 0..63 row-panel
    const char* panel = g_pp + ((size_t)pr * 64 + pk) * PANEL_A;
    const int tid = threadIdx.x;
    const int col = tid & 31;
    const int rg  = tid >> 5;    // 8 groups of 16 rows

    const uint32_t cbase = ((col & 31) >> 3) * 128 + (col & 7) * 2;
    float s = 0.f;
#pragma unroll
    for (int r = rg * 16; r < rg * 16 + 16; r++) {
        uint32_t off = (uint32_t)((r & 7) * 16 + 4 * (r >> 3) * 128) + cbase;
        s += __bfloat162float(*(const bf16*)(panel + off))
           + __bfloat162float(*(const bf16*)(panel + off + 8192));
    }
    __shared__ float part[256];
    part[tid] = s;
    __syncthreads();
    if (tid < 32) {
        float t = 0.f;
#pragma unroll
        for (int j = 0; j < 8; j++) t += part[tid + 32 * j];
        const int batch = pr >> 4;
        atomicAdd(out + batch * SEQ + pk * 32 + tid, t);
    }
}

// ---------------------------------------------------------------------------
extern "C" void kernel_launch(void* const* d_in, const int* in_sizes, int n_in,
                              void* d_out, int out_size)
{
    const float* x  = (const float*)d_in[0];
    const float* Wq = (const float*)d_in[1];
    const float* bq = (const float*)d_in[2];
    const float* Wk = (const float*)d_in[3];
    const float* bk = (const float*)d_in[4];
    const float* Wv = (const float*)d_in[5];
    const float* bv = (const float*)d_in[6];

    float* ctx = (float*)d_out;
    float* sc  = ctx + (size_t)BATCH * SEQ * HDIM;

    cudaFuncSetAttribute((const void*)qkv_tc,
                         cudaFuncAttributeMaxDynamicSharedMemorySize, SMEM_BYTES);
    cudaFuncSetAttribute((const void*)scores_tc,
                         cudaFuncAttributeMaxDynamicSharedMemorySize, SMEM_BYTES);
    cudaFuncSetAttribute((const void*)context_tc,
                         cudaFuncAttributeMaxDynamicSharedMemorySize, SMEM_BYTES);

    char *xp, *wqp, *wkp, *wvp;
    cudaGetSymbolAddress((void**)&xp,  g_xp);
    cudaGetSymbolAddress((void**)&wqp, g_wqp);
    cudaGetSymbolAddress((void**)&wkp, g_wkp);
    cudaGetSymbolAddress((void**)&wvp, g_wvp);

    cudaMemsetAsync(sc, 0, (size_t)BATCH * SEQ * sizeof(float));

    split_fused<<<8192 + 3 * 1024, 256>>>(x, Wq, Wk, Wv, xp, wqp, wkp, wvp);

    qkv_tc<<<dim3(HDIM / 256, MTOT / 128, 3), NTHREADS, SMEM_BYTES>>>(bq, bk, bv);
    scores_tc<<<dim3(SEQ / 256, SEQ / 128, BATCH), NTHREADS, SMEM_BYTES>>>();
    softmax_kernel<<<MTOT, 256>>>();
    colsum_kernel<<<dim3(64, 64), 256>>>(sc);
    context_tc<<<dim3(HDIM / 256, SEQ / 128, BATCH), NTHREADS, SMEM_BYTES>>>(ctx);
}